// round 4
// baseline (speedup 1.0000x reference)
#include <cuda_runtime.h>
#include <cuda_bf16.h>

#define HID 128
#define MLPD 64
#define MAX_NODES 50000
#define TILE_N 32

// Scratch: per-node projections. P[n][0:64] = emb[n] @ W1[0:128] + b1
//          P[n][64:128] = emb[n] @ W1[128:256]
__device__ float g_P[(size_t)MAX_NODES * HID];

// ---------------------------------------------------------------------------
// Kernel A: node projection GEMM  [n_nodes,128] x [128,128] -> P
// ---------------------------------------------------------------------------
__global__ void __launch_bounds__(128) proj_kernel(
    const float* __restrict__ emb,   // [n_nodes, 128]
    const float* __restrict__ W1,    // [256, 64] row-major
    const float* __restrict__ b1,    // [64]
    float* __restrict__ P,
    int n_nodes)
{
    __shared__ float Ws[HID * MLPD];       // 32 KB: current half of W1
    __shared__ float Es[TILE_N * HID];     // 16 KB: emb tile

    const int tid = threadIdx.x;
    const int base = blockIdx.x * TILE_N;

    #pragma unroll
    for (int i = 0; i < (TILE_N * HID) / 128; i++) {
        int idx = i * 128 + tid;
        int n = base + idx / HID;
        Es[idx] = (n < n_nodes) ? emb[(size_t)n * HID + (idx % HID)] : 0.0f;
    }

    const int jg = tid & 15;
    const int ng = tid >> 4;
    const int jbase = jg * 4;
    const int nbase = ng * 4;

    for (int half = 0; half < 2; half++) {
        __syncthreads();
        #pragma unroll
        for (int i = 0; i < (HID * MLPD) / 128; i++) {
            int idx = i * 128 + tid;
            Ws[idx] = W1[half * (HID * MLPD) + idx];
        }
        __syncthreads();

        float acc[4][4];
        #pragma unroll
        for (int t = 0; t < 4; t++)
            #pragma unroll
            for (int c = 0; c < 4; c++) acc[t][c] = 0.0f;

        #pragma unroll 4
        for (int k = 0; k < HID; k++) {
            float4 w = *reinterpret_cast<const float4*>(&Ws[k * MLPD + jbase]);
            float e0 = Es[(nbase + 0) * HID + k];
            float e1 = Es[(nbase + 1) * HID + k];
            float e2 = Es[(nbase + 2) * HID + k];
            float e3 = Es[(nbase + 3) * HID + k];
            acc[0][0] = fmaf(e0, w.x, acc[0][0]); acc[0][1] = fmaf(e0, w.y, acc[0][1]);
            acc[0][2] = fmaf(e0, w.z, acc[0][2]); acc[0][3] = fmaf(e0, w.w, acc[0][3]);
            acc[1][0] = fmaf(e1, w.x, acc[1][0]); acc[1][1] = fmaf(e1, w.y, acc[1][1]);
            acc[1][2] = fmaf(e1, w.z, acc[1][2]); acc[1][3] = fmaf(e1, w.w, acc[1][3]);
            acc[2][0] = fmaf(e2, w.x, acc[2][0]); acc[2][1] = fmaf(e2, w.y, acc[2][1]);
            acc[2][2] = fmaf(e2, w.z, acc[2][2]); acc[2][3] = fmaf(e2, w.w, acc[2][3]);
            acc[3][0] = fmaf(e3, w.x, acc[3][0]); acc[3][1] = fmaf(e3, w.y, acc[3][1]);
            acc[3][2] = fmaf(e3, w.z, acc[3][2]); acc[3][3] = fmaf(e3, w.w, acc[3][3]);
        }

        if (half == 0) {
            float4 bv = *reinterpret_cast<const float4*>(&b1[jbase]);
            #pragma unroll
            for (int t = 0; t < 4; t++) {
                acc[t][0] += bv.x; acc[t][1] += bv.y;
                acc[t][2] += bv.z; acc[t][3] += bv.w;
            }
        }

        #pragma unroll
        for (int t = 0; t < 4; t++) {
            int n = base + nbase + t;
            if (n < n_nodes) {
                float4 o = make_float4(acc[t][0], acc[t][1], acc[t][2], acc[t][3]);
                *reinterpret_cast<float4*>(&P[(size_t)n * HID + half * MLPD + jbase]) = o;
            }
        }
    }
}

// ---------------------------------------------------------------------------
// Kernel B: per-edge  out[e] = relu(P_src[src] + P_dst[dst]) . W2 + b2
// One warp per edge. Lanes 0-15: src half-row, lanes 16-31: dst half-row.
// edge_index is INT32 (JAX x64 disabled downcasts int64 -> int32).
// ---------------------------------------------------------------------------
__global__ void __launch_bounds__(256) edge_kernel(
    const int* __restrict__ ei,         // [2, E] int32
    const float* __restrict__ P,
    const float* __restrict__ W2,       // [64]
    const float* __restrict__ b2,       // [1]
    float* __restrict__ out,
    int E)
{
    int warp = (blockIdx.x * blockDim.x + threadIdx.x) >> 5;
    if (warp >= E) return;
    const int lane = threadIdx.x & 31;
    const int half = lane >> 4;           // 0 = src features, 1 = dst features
    const int fi = (lane & 15) * 4;       // feature base within the 64

    int row = __ldg(&ei[(size_t)half * E + warp]);
    const float4 v = *reinterpret_cast<const float4*>(
        &P[(size_t)row * HID + half * MLPD + fi]);

    float4 u;
    u.x = __shfl_xor_sync(0xffffffffu, v.x, 16);
    u.y = __shfl_xor_sync(0xffffffffu, v.y, 16);
    u.z = __shfl_xor_sync(0xffffffffu, v.z, 16);
    u.w = __shfl_xor_sync(0xffffffffu, v.w, 16);

    float4 w2v = *reinterpret_cast<const float4*>(&W2[fi]);
    float s;
    s  = fmaxf(v.x + u.x, 0.0f) * w2v.x;
    s += fmaxf(v.y + u.y, 0.0f) * w2v.y;
    s += fmaxf(v.z + u.z, 0.0f) * w2v.z;
    s += fmaxf(v.w + u.w, 0.0f) * w2v.w;

    s += __shfl_xor_sync(0xffffffffu, s, 8);
    s += __shfl_xor_sync(0xffffffffu, s, 4);
    s += __shfl_xor_sync(0xffffffffu, s, 2);
    s += __shfl_xor_sync(0xffffffffu, s, 1);

    if (lane == 0) out[warp] = s + b2[0];
}

extern "C" void kernel_launch(void* const* d_in, const int* in_sizes, int n_in,
                              void* d_out, int out_size)
{
    // Resolve input slots by element count (robust to metadata ordering).
    // node_emb: N*128 (largest), edge_index: 2*E, W1: 16384, b2: 1,
    // b1 & W2: both 64 -> first-seen is b1, second is W2 (declaration order).
    const float* node_emb = nullptr;
    const int*   edge_idx = nullptr;
    const float* W1 = nullptr;
    const float* b1 = nullptr;
    const float* W2 = nullptr;
    const float* b2 = nullptr;
    // defaults by declared order
    int i_emb = 0, i_ei = 1, i_w1 = 2, i_b1 = 3, i_w2 = 4, i_b2 = 5;
    if (n_in == 6) {
        int seen64 = 0;
        for (int i = 0; i < n_in; i++) {
            int s = in_sizes[i];
            if (s == 16384) i_w1 = i;
            else if (s == 1) i_b2 = i;
            else if (s == 64) { if (seen64++ == 0) i_b1 = i; else i_w2 = i; }
            else if (s >= 1000000) {
                // node_emb (6.4M) vs edge_index (1.6M): larger is emb
                if (s > 3000000) i_emb = i; else i_ei = i;
            }
        }
    }
    node_emb = (const float*)d_in[i_emb];
    edge_idx = (const int*)  d_in[i_ei];
    W1       = (const float*)d_in[i_w1];
    b1       = (const float*)d_in[i_b1];
    W2       = (const float*)d_in[i_w2];
    b2       = (const float*)d_in[i_b2];
    float* out = (float*)d_out;

    const int n_nodes = in_sizes[i_emb] / HID;
    const int E       = in_sizes[i_ei] / 2;

    float* P = nullptr;
    cudaGetSymbolAddress((void**)&P, g_P);

    proj_kernel<<<(n_nodes + TILE_N - 1) / TILE_N, 128>>>(node_emb, W1, b1, P, n_nodes);
    edge_kernel<<<(E + 7) / 8, 256>>>(edge_idx, P, W2, b2, out, E);
}

// round 8
// speedup vs baseline: 1.0178x; 1.0178x over previous
#include <cuda_runtime.h>
#include <cuda_bf16.h>

#define HID 128
#define MLPD 64
#define MAX_NODES 50000
#define TILE_N 32

// Scratch: per-node projections. P[n][0:64] = emb[n] @ W1[0:128] + b1
//          P[n][64:128] = emb[n] @ W1[128:256]
__device__ float g_P[(size_t)MAX_NODES * HID];

// ---------------------------------------------------------------------------
// Kernel A: node projection GEMM  [n_nodes,128] x [128,128] -> P
// (measured ~86% of fp32 FMA peak — unchanged)
// ---------------------------------------------------------------------------
__global__ void __launch_bounds__(128) proj_kernel(
    const float* __restrict__ emb,   // [n_nodes, 128]
    const float* __restrict__ W1,    // [256, 64] row-major
    const float* __restrict__ b1,    // [64]
    float* __restrict__ P,
    int n_nodes)
{
    __shared__ float Ws[HID * MLPD];       // 32 KB: current half of W1
    __shared__ float Es[TILE_N * HID];     // 16 KB: emb tile

    const int tid = threadIdx.x;
    const int base = blockIdx.x * TILE_N;

    #pragma unroll
    for (int i = 0; i < (TILE_N * HID) / 128; i++) {
        int idx = i * 128 + tid;
        int n = base + idx / HID;
        Es[idx] = (n < n_nodes) ? emb[(size_t)n * HID + (idx % HID)] : 0.0f;
    }

    const int jg = tid & 15;
    const int ng = tid >> 4;
    const int jbase = jg * 4;
    const int nbase = ng * 4;

    for (int half = 0; half < 2; half++) {
        __syncthreads();
        #pragma unroll
        for (int i = 0; i < (HID * MLPD) / 128; i++) {
            int idx = i * 128 + tid;
            Ws[idx] = W1[half * (HID * MLPD) + idx];
        }
        __syncthreads();

        float acc[4][4];
        #pragma unroll
        for (int t = 0; t < 4; t++)
            #pragma unroll
            for (int c = 0; c < 4; c++) acc[t][c] = 0.0f;

        #pragma unroll 4
        for (int k = 0; k < HID; k++) {
            float4 w = *reinterpret_cast<const float4*>(&Ws[k * MLPD + jbase]);
            float e0 = Es[(nbase + 0) * HID + k];
            float e1 = Es[(nbase + 1) * HID + k];
            float e2 = Es[(nbase + 2) * HID + k];
            float e3 = Es[(nbase + 3) * HID + k];
            acc[0][0] = fmaf(e0, w.x, acc[0][0]); acc[0][1] = fmaf(e0, w.y, acc[0][1]);
            acc[0][2] = fmaf(e0, w.z, acc[0][2]); acc[0][3] = fmaf(e0, w.w, acc[0][3]);
            acc[1][0] = fmaf(e1, w.x, acc[1][0]); acc[1][1] = fmaf(e1, w.y, acc[1][1]);
            acc[1][2] = fmaf(e1, w.z, acc[1][2]); acc[1][3] = fmaf(e1, w.w, acc[1][3]);
            acc[2][0] = fmaf(e2, w.x, acc[2][0]); acc[2][1] = fmaf(e2, w.y, acc[2][1]);
            acc[2][2] = fmaf(e2, w.z, acc[2][2]); acc[2][3] = fmaf(e2, w.w, acc[2][3]);
            acc[3][0] = fmaf(e3, w.x, acc[3][0]); acc[3][1] = fmaf(e3, w.y, acc[3][1]);
            acc[3][2] = fmaf(e3, w.z, acc[3][2]); acc[3][3] = fmaf(e3, w.w, acc[3][3]);
        }

        if (half == 0) {
            float4 bv = *reinterpret_cast<const float4*>(&b1[jbase]);
            #pragma unroll
            for (int t = 0; t < 4; t++) {
                acc[t][0] += bv.x; acc[t][1] += bv.y;
                acc[t][2] += bv.z; acc[t][3] += bv.w;
            }
        }

        #pragma unroll
        for (int t = 0; t < 4; t++) {
            int n = base + nbase + t;
            if (n < n_nodes) {
                float4 o = make_float4(acc[t][0], acc[t][1], acc[t][2], acc[t][3]);
                *reinterpret_cast<float4*>(&P[(size_t)n * HID + half * MLPD + jbase]) = o;
            }
        }
    }
}

// ---------------------------------------------------------------------------
// Kernel B: per-edge  out[e] = relu(P_src[src][0:64] + P_dst[dst][64:128]).W2 + b2
// Half-warp (16 lanes) per edge PAIR: lane g covers feature block 4g of
// BOTH edges of the pair. 4 edges per warp. No cross-half combine shuffles;
// 4-level xor reduction within each 16-lane group serves 2 edges at once.
// ---------------------------------------------------------------------------
__global__ void __launch_bounds__(256) edge_kernel(
    const int* __restrict__ ei,         // [2, E] int32
    const float* __restrict__ P,
    const float* __restrict__ W2,       // [64]
    const float* __restrict__ b2,       // [1]
    float* __restrict__ out,
    int E)
{
    const int lane = threadIdx.x & 31;
    const int g    = lane & 15;          // position within half-warp
    const int hw   = lane >> 4;          // which half-warp (0/1)
    const int warp = (blockIdx.x * blockDim.x + threadIdx.x) >> 5;

    // This half-warp handles edges e0, e0+1
    const int e0 = warp * 4 + hw * 2;
    if (e0 >= E) return;                 // uniform per half-warp... guard below keeps shfl safe
    const int e1c = (e0 + 1 < E) ? (e0 + 1) : e0;   // clamp for safe loads

    const int fi = g * 4;

    // Broadcast index loads (uniform within half-warp)
    const int rs0 = __ldg(&ei[e0]);
    const int rd0 = __ldg(&ei[(size_t)E + e0]);
    const int rs1 = __ldg(&ei[e1c]);
    const int rd1 = __ldg(&ei[(size_t)E + e1c]);

    // 4 independent 16B gathers in flight
    const float4 a0 = *reinterpret_cast<const float4*>(&P[(size_t)rs0 * HID + fi]);
    const float4 b0 = *reinterpret_cast<const float4*>(&P[(size_t)rd0 * HID + MLPD + fi]);
    const float4 a1 = *reinterpret_cast<const float4*>(&P[(size_t)rs1 * HID + fi]);
    const float4 b1v = *reinterpret_cast<const float4*>(&P[(size_t)rd1 * HID + MLPD + fi]);

    const float4 w = *reinterpret_cast<const float4*>(&W2[fi]);

    float s0, s1;
    s0  = fmaxf(a0.x + b0.x, 0.0f) * w.x;
    s0 += fmaxf(a0.y + b0.y, 0.0f) * w.y;
    s0 += fmaxf(a0.z + b0.z, 0.0f) * w.z;
    s0 += fmaxf(a0.w + b0.w, 0.0f) * w.w;

    s1  = fmaxf(a1.x + b1v.x, 0.0f) * w.x;
    s1 += fmaxf(a1.y + b1v.y, 0.0f) * w.y;
    s1 += fmaxf(a1.z + b1v.z, 0.0f) * w.z;
    s1 += fmaxf(a1.w + b1v.w, 0.0f) * w.w;

    // Reduce over the 16-lane group (xor < 16 keeps it within the group)
    #pragma unroll
    for (int m = 8; m >= 1; m >>= 1) {
        s0 += __shfl_xor_sync(0xffffffffu, s0, m);
        s1 += __shfl_xor_sync(0xffffffffu, s1, m);
    }

    if (g == 0) {
        const float bias = b2[0];
        out[e0] = s0 + bias;
        if (e0 + 1 < E) out[e0 + 1] = s1 + bias;
    }
}

extern "C" void kernel_launch(void* const* d_in, const int* in_sizes, int n_in,
                              void* d_out, int out_size)
{
    // Resolve input slots by element count (robust to metadata ordering).
    int i_emb = 0, i_ei = 1, i_w1 = 2, i_b1 = 3, i_w2 = 4, i_b2 = 5;
    if (n_in == 6) {
        int seen64 = 0;
        for (int i = 0; i < n_in; i++) {
            int s = in_sizes[i];
            if (s == 16384) i_w1 = i;
            else if (s == 1) i_b2 = i;
            else if (s == 64) { if (seen64++ == 0) i_b1 = i; else i_w2 = i; }
            else if (s >= 1000000) {
                if (s > 3000000) i_emb = i; else i_ei = i;
            }
        }
    }
    const float* node_emb = (const float*)d_in[i_emb];
    const int*   edge_idx = (const int*)  d_in[i_ei];
    const float* W1       = (const float*)d_in[i_w1];
    const float* b1       = (const float*)d_in[i_b1];
    const float* W2       = (const float*)d_in[i_w2];
    const float* b2       = (const float*)d_in[i_b2];
    float* out = (float*)d_out;

    const int n_nodes = in_sizes[i_emb] / HID;
    const int E       = in_sizes[i_ei] / 2;

    float* P = nullptr;
    cudaGetSymbolAddress((void**)&P, g_P);

    proj_kernel<<<(n_nodes + TILE_N - 1) / TILE_N, 128>>>(node_emb, W1, b1, P, n_nodes);

    // 4 edges per warp, 8 warps per block -> 32 edges per block
    int blocks = (E + 31) / 32;
    edge_kernel<<<blocks, 256>>>(edge_idx, P, W2, b2, out, E);
}

// round 12
// speedup vs baseline: 1.4638x; 1.4382x over previous
#include <cuda_runtime.h>
#include <cuda_fp16.h>

#define HID 128
#define MLPD 64
#define MAX_NODES 50000
#define TILE_N 32
#define ES_STRIDE 36   // padded row stride for transposed emb tile (4-way bank spread, 16B-aligned)

// Scratch: per-node projections in FP16.
// P[n][0:64] = emb[n] @ W1[0:128] + b1 ;  P[n][64:128] = emb[n] @ W1[128:256]
__device__ __half g_Ph[(size_t)MAX_NODES * HID];

#define FMA2(d, a, b, c) \
    asm("fma.rn.f32x2 %0, %1, %2, %3;" : "=l"(d) : "l"(a), "l"(b), "l"(c))
#define ADD2(d, a, b) \
    asm("add.rn.f32x2 %0, %1, %2;" : "=l"(d) : "l"(a), "l"(b))
#define DUP2(d, f) \
    asm("mov.b64 %0, {%1, %1};" : "=l"(d) : "r"(__float_as_uint(f)))

__device__ __forceinline__ float2 unpack2(unsigned long long v) {
    unsigned int lo, hi;
    asm("mov.b64 {%0, %1}, %2;" : "=r"(lo), "=r"(hi) : "l"(v));
    return make_float2(__uint_as_float(lo), __uint_as_float(hi));
}

// ---------------------------------------------------------------------------
// Kernel A: node projection GEMM  [n_nodes,128] x [128,128] -> P (fp16 out)
// Packed f32x2 FMA: 8 FFMA2/k/thread instead of 16 FFMA. Es transposed [k][n].
// ---------------------------------------------------------------------------
__global__ void __launch_bounds__(128) proj_kernel(
    const float* __restrict__ emb,   // [n_nodes, 128]
    const float* __restrict__ W1,    // [256, 64] row-major
    const float* __restrict__ b1,    // [64]
    __half* __restrict__ P,
    int n_nodes)
{
    __shared__ float Ws[HID * MLPD];            // 32 KB: current half of W1
    __shared__ float Es[HID * ES_STRIDE];       // 18 KB: emb tile, transposed Es[k][n]

    const int tid = threadIdx.x;
    const int base = blockIdx.x * TILE_N;

    // Fill Es transposed: Es[k=tid][n=i]  (coalesced global reads, 32 loads in flight)
    #pragma unroll
    for (int i = 0; i < TILE_N; i++) {
        int node = base + i;
        float v = (node < n_nodes) ? emb[(size_t)node * HID + tid] : 0.0f;
        Es[tid * ES_STRIDE + i] = v;
    }

    const int jg = tid & 15;          // 16 j-groups of 4 outputs
    const int ng = tid >> 4;          // 8 n-groups of 4 nodes
    const int jbase = jg * 4;
    const int nbase = ng * 4;

    for (int half = 0; half < 2; half++) {
        __syncthreads();
        #pragma unroll
        for (int i = 0; i < (HID * MLPD) / 128; i++) {
            int idx = i * 128 + tid;
            Ws[idx] = W1[half * (HID * MLPD) + idx];
        }
        __syncthreads();

        unsigned long long acc[4][2];
        #pragma unroll
        for (int t = 0; t < 4; t++) { acc[t][0] = 0ull; acc[t][1] = 0ull; }

        #pragma unroll 4
        for (int k = 0; k < HID; k++) {
            // w pair-packed for free: float4 bits == {f32x2, f32x2}
            ulonglong2 wp = *reinterpret_cast<const ulonglong2*>(&Ws[k * MLPD + jbase]);
            float4 ev = *reinterpret_cast<const float4*>(&Es[k * ES_STRIDE + nbase]);
            unsigned long long e0, e1, e2, e3;
            DUP2(e0, ev.x); DUP2(e1, ev.y); DUP2(e2, ev.z); DUP2(e3, ev.w);
            FMA2(acc[0][0], e0, wp.x, acc[0][0]); FMA2(acc[0][1], e0, wp.y, acc[0][1]);
            FMA2(acc[1][0], e1, wp.x, acc[1][0]); FMA2(acc[1][1], e1, wp.y, acc[1][1]);
            FMA2(acc[2][0], e2, wp.x, acc[2][0]); FMA2(acc[2][1], e2, wp.y, acc[2][1]);
            FMA2(acc[3][0], e3, wp.x, acc[3][0]); FMA2(acc[3][1], e3, wp.y, acc[3][1]);
        }

        if (half == 0) {
            ulonglong2 bp = *reinterpret_cast<const ulonglong2*>(&b1[jbase]);
            #pragma unroll
            for (int t = 0; t < 4; t++) {
                ADD2(acc[t][0], acc[t][0], bp.x);
                ADD2(acc[t][1], acc[t][1], bp.y);
            }
        }

        #pragma unroll
        for (int t = 0; t < 4; t++) {
            int node = base + nbase + t;
            if (node < n_nodes) {
                float2 lo = unpack2(acc[t][0]);
                float2 hi = unpack2(acc[t][1]);
                __half2 h0 = __floats2half2_rn(lo.x, lo.y);
                __half2 h1 = __floats2half2_rn(hi.x, hi.y);
                uint2 st;
                st.x = *reinterpret_cast<unsigned int*>(&h0);
                st.y = *reinterpret_cast<unsigned int*>(&h1);
                *reinterpret_cast<uint2*>(&P[(size_t)node * HID + half * MLPD + jbase]) = st;
            }
        }
    }
}

// ---------------------------------------------------------------------------
// Kernel B: out[e] = relu(P_src[src][0:64] + P_dst[dst][64:128]) . W2 + b2
// fp16 P: 8 lanes per edge, 16B (8 halves) per lane -> one 128B line per row.
// 4 edges per warp. 32-bit addressing throughout.
// ---------------------------------------------------------------------------
struct __align__(16) H2x4 { __half2 a, b, c, d; };

__global__ void __launch_bounds__(256) edge_kernel(
    const int* __restrict__ ei,          // [2, E] int32
    const __half* __restrict__ P,
    const float* __restrict__ W2,        // [64]
    const float* __restrict__ b2,        // [1]
    float* __restrict__ out,
    int E)
{
    const int lane = threadIdx.x & 31;
    const int q    = lane & 7;           // position within 8-lane group
    const int grp  = lane >> 3;          // group 0..3 -> edge within warp
    const int warp = (blockIdx.x * blockDim.x + threadIdx.x) >> 5;

    const int e = warp * 4 + grp;
    if (warp * 4 >= E) return;
    const int ec = (e < E) ? e : (E - 1);

    const int rs = __ldg(&ei[ec]);
    const int rd = __ldg(&ei[E + ec]);

    const int fo = q * 8;
    const H2x4 av = *reinterpret_cast<const H2x4*>(&P[rs * HID + fo]);
    const H2x4 bv = *reinterpret_cast<const H2x4*>(&P[rd * HID + MLPD + fo]);

    const __half2 z = __float2half2_rn(0.0f);
    const __half2 h0 = __hmax2(__hadd2(av.a, bv.a), z);
    const __half2 h1 = __hmax2(__hadd2(av.b, bv.b), z);
    const __half2 h2 = __hmax2(__hadd2(av.c, bv.c), z);
    const __half2 h3 = __hmax2(__hadd2(av.d, bv.d), z);

    const float4 w0 = *reinterpret_cast<const float4*>(&W2[fo]);
    const float4 w1 = *reinterpret_cast<const float4*>(&W2[fo + 4]);

    const float2 f0 = __half22float2(h0);
    const float2 f1 = __half22float2(h1);
    const float2 f2 = __half22float2(h2);
    const float2 f3 = __half22float2(h3);

    float s;
    s  = f0.x * w0.x; s = fmaf(f0.y, w0.y, s);
    s  = fmaf(f1.x, w0.z, s); s = fmaf(f1.y, w0.w, s);
    s  = fmaf(f2.x, w1.x, s); s = fmaf(f2.y, w1.y, s);
    s  = fmaf(f3.x, w1.z, s); s = fmaf(f3.y, w1.w, s);

    // Reduce over the 8-lane group
    s += __shfl_xor_sync(0xffffffffu, s, 4);
    s += __shfl_xor_sync(0xffffffffu, s, 2);
    s += __shfl_xor_sync(0xffffffffu, s, 1);

    if (q == 0 && e < E) out[e] = s + __ldg(b2);
}

extern "C" void kernel_launch(void* const* d_in, const int* in_sizes, int n_in,
                              void* d_out, int out_size)
{
    // Resolve input slots by element count (robust to metadata ordering).
    int i_emb = 0, i_ei = 1, i_w1 = 2, i_b1 = 3, i_w2 = 4, i_b2 = 5;
    if (n_in == 6) {
        int seen64 = 0;
        for (int i = 0; i < n_in; i++) {
            int s = in_sizes[i];
            if (s == 16384) i_w1 = i;
            else if (s == 1) i_b2 = i;
            else if (s == 64) { if (seen64++ == 0) i_b1 = i; else i_w2 = i; }
            else if (s >= 1000000) {
                if (s > 3000000) i_emb = i; else i_ei = i;
            }
        }
    }
    const float* node_emb = (const float*)d_in[i_emb];
    const int*   edge_idx = (const int*)  d_in[i_ei];
    const float* W1       = (const float*)d_in[i_w1];
    const float* b1       = (const float*)d_in[i_b1];
    const float* W2       = (const float*)d_in[i_w2];
    const float* b2       = (const float*)d_in[i_b2];
    float* out = (float*)d_out;

    const int n_nodes = in_sizes[i_emb] / HID;
    const int E       = in_sizes[i_ei] / 2;

    __half* P = nullptr;
    cudaGetSymbolAddress((void**)&P, g_Ph);

    proj_kernel<<<(n_nodes + TILE_N - 1) / TILE_N, 128>>>(node_emb, W1, b1, P, n_nodes);

    // 4 edges/warp, 8 warps/block -> 32 edges/block
    edge_kernel<<<(E + 31) / 32, 256>>>(edge_idx, P, W2, b2, out, E);
}